// round 15
// baseline (speedup 1.0000x reference)
#include <cuda_runtime.h>
#include <cuda_fp16.h>
#include <cstdint>

// Problem constants
#define BATCH 4
#define TLEN  4096
#define DIM   1024
#define NH    16
#define HD    64
#define TSPL  16             // context T-slices

// ---------------------------------------------------------------------------
// Scratch (device globals; no allocation allowed)
// ---------------------------------------------------------------------------
__device__ static __align__(256) __half g_kvh[(long)BATCH * TLEN * 2 * DIM]; // ek|v fp16
__device__ static __align__(256) float g_Z [BATCH * DIM];
__device__ static __align__(256) float g_zero[DIM];
__device__ static __align__(256) float g_cb[BATCH * DIM];
__device__ static __align__(256) float g_Cp[BATCH * NH * TSPL * HD * HD];
__device__ static __align__(256) float g_Cn[BATCH * NH * HD * HD];

__device__ static __align__(256) __half g_zs [(long)BATCH * TLEN * DIM];
__device__ static __align__(256) __half g_xs [(long)BATCH * TLEN * DIM];
__device__ static __align__(256) __half g_wkvs[(long)2 * DIM * DIM];
__device__ static __align__(256) __half g_wq16[(long)DIM * DIM];       // w_q plain cast
__device__ static __align__(256) __half g_Es  [(long)BATCH * DIM * DIM]; // E^T fp16
__device__ static __align__(256) __half g_Fs  [(long)BATCH * DIM * DIM]; // F^T fp16

// ---------------------------------------------------------------------------
// Helpers
// ---------------------------------------------------------------------------
#define SW128(o) ((o) ^ (((o) >> 3) & 0x70))

static __device__ __forceinline__ uint32_t su32(const void* p) {
    uint32_t a;
    asm("{ .reg .u64 t; cvta.to.shared.u64 t, %1; cvt.u32.u64 %0, t; }" : "=r"(a) : "l"(p));
    return a;
}

#define CP16(dst, src)   asm volatile("cp.async.cg.shared.global [%0], [%1], 16;" :: "r"(dst), "l"(src))
#define CP_COMMIT()      asm volatile("cp.async.commit_group;" ::: "memory")
#define CP_WAIT(n)       asm volatile("cp.async.wait_group %0;" :: "n"(n) : "memory")

#define LDSM4(r0, r1, r2, r3, addr) \
    asm volatile("ldmatrix.sync.aligned.m8n8.x4.shared.b16 {%0,%1,%2,%3}, [%4];" \
        : "=r"(r0), "=r"(r1), "=r"(r2), "=r"(r3) : "r"(addr))

#define LDSM4T(r0, r1, r2, r3, addr) \
    asm volatile("ldmatrix.sync.aligned.m8n8.x4.trans.shared.b16 {%0,%1,%2,%3}, [%4];" \
        : "=r"(r0), "=r"(r1), "=r"(r2), "=r"(r3) : "r"(addr))

#define MMA16816(d, a, b) \
    asm volatile("mma.sync.aligned.m16n8k16.row.col.f32.f16.f16.f32 " \
        "{%0,%1,%2,%3},{%4,%5,%6,%7},{%8,%9},{%0,%1,%2,%3};" \
        : "+f"((d)[0]), "+f"((d)[1]), "+f"((d)[2]), "+f"((d)[3]) \
        : "r"((a)[0]), "r"((a)[1]), "r"((a)[2]), "r"((a)[3]), "r"((b)[0]), "r"((b)[1]))

// ---------------------------------------------------------------------------
// mma.sync fp16 GEMM:  C[M,N] = A[M,1024] * B[N,1024]^T + bias
// BM=128, BN=256, BK=64; 512 threads (16 warps, 2x8 of 64x32 tiles);
// 3-stage cp.async (144 KB smem, 1 CTA/SM = 16 warps/SM), ONE sync per k-tile.
// split=1: write fp16 rows of width N into Cs (batched via sC).
// kexp>0: cols < kexp -> exp() after bias (no max shift; k~N(0,1) safe) and
//         per-(batch,col) partial sums atomicAdd'ed into g_Z.
// grid = (N/256, M/128, batch)
// ---------------------------------------------------------------------------
#define GNK      16
#define AH_OFF   0
#define BB_OFF   16384
#define STG_B    49152              // 48 KB
#define GSMEM    (3 * STG_B)        // 144 KB

extern __shared__ __align__(1024) char gsm_raw[];

__global__ __launch_bounds__(512, 1)
void gemm_mma(const __half* __restrict__ A, const __half* __restrict__ B,
              const float* __restrict__ bias, float* __restrict__ Cf,
              __half* __restrict__ Cs, int N, int split, int kexp,
              long sA, long sB, long sC, long sBias)
{
    A += blockIdx.z * sA; B += blockIdx.z * sB; bias += blockIdx.z * sBias;
    const long coff = (long)blockIdx.z * sC;
    if (Cf) Cf += coff;
    if (Cs) Cs += coff;
    const int m0 = blockIdx.y * 128;
    const int n0 = blockIdx.x * 256;
    const uint32_t sbase = su32(gsm_raw);
    const int tid = threadIdx.x, wid = tid >> 5, lane = tid & 31;

    const __half* Arow = A + (long)m0 * DIM;
    const __half* Brow = B + (long)n0 * DIM;

    auto load_tile = [&](int kt, int s) {
        const uint32_t st = sbase + s * STG_B;
        const int kc = kt * 64;
#pragma unroll
        for (int it = 0; it < 6; it++) {
            int i = tid + it * 512;
            if (it < 2) {                          // A: i in [0,1024)
                int row = i >> 3, ch = (i & 7) * 16;
                CP16(st + AH_OFF + SW128(row * 128 + ch),
                     Arow + (long)row * DIM + kc + ch / 2);
            } else {                               // B: j in [0,2048)
                int j = i - 1024;
                int row = j >> 3, ch = (j & 7) * 16;
                CP16(st + BB_OFF + SW128(row * 128 + ch),
                     Brow + (long)row * DIM + kc + ch / 2);
            }
        }
    };

    float acc[4][4][4];
#pragma unroll
    for (int mf = 0; mf < 4; mf++)
#pragma unroll
        for (int nf = 0; nf < 4; nf++)
#pragma unroll
            for (int r = 0; r < 4; r++) acc[mf][nf][r] = 0.f;

    const int wm = wid >> 3;                                      // 0..1
    const int wn = wid & 7;                                       // 0..7
    const int a_row = wm * 64 + (lane & 15);                      // + mf*16
    const int a_sec = (lane >> 4) * 16;
    const int b_row = wn * 32 + (lane & 7) + ((lane >> 4) << 3);  // + nf2*16
    const int b_sec = ((lane >> 3) & 1) * 16;

    // prologue: stages 0, 1
    load_tile(0, 0); CP_COMMIT();
    load_tile(1, 1); CP_COMMIT();

    int s_cur = 0, s_nxt = 2;
    for (int kt = 0; kt < GNK; kt++) {
        if (kt < GNK - 1) CP_WAIT(1); else CP_WAIT(0);
        __syncthreads();                 // stage s_cur ready; prior reads done
        if (kt + 2 < GNK) { load_tile(kt + 2, s_nxt); CP_COMMIT(); }

        const uint32_t st = sbase + s_cur * STG_B;
#pragma unroll
        for (int ks = 0; ks < 4; ks++) {
            uint32_t bf[4][2];
#pragma unroll
            for (int nf2 = 0; nf2 < 2; nf2++)
                LDSM4(bf[nf2 * 2][0], bf[nf2 * 2][1], bf[nf2 * 2 + 1][0], bf[nf2 * 2 + 1][1],
                      st + BB_OFF + SW128((b_row + nf2 * 16) * 128 + ks * 32 + b_sec));
#pragma unroll
            for (int mf = 0; mf < 4; mf++) {
                uint32_t ah[4];
                LDSM4(ah[0], ah[1], ah[2], ah[3],
                      st + AH_OFF + SW128((a_row + mf * 16) * 128 + ks * 32 + a_sec));
#pragma unroll
                for (int nf = 0; nf < 4; nf++)
                    MMA16816(acc[mf][nf], ah, bf[nf]);
            }
        }
        if (++s_cur == 3) s_cur = 0;
        if (++s_nxt == 3) s_nxt = 0;
    }

    // Epilogue
#pragma unroll
    for (int nf = 0; nf < 4; nf++) {
        const int col = n0 + wn * 32 + nf * 8 + (lane & 3) * 2;
        const float b0 = __ldg(bias + col), b1 = __ldg(bias + col + 1);
        const bool doexp = (col < kexp);     // uniform per 8-col group
        float s0 = 0.f, s1 = 0.f;
#pragma unroll
        for (int mf = 0; mf < 4; mf++) {
            const int row = m0 + wm * 64 + mf * 16 + (lane >> 2);
            float v0 = acc[mf][nf][0] + b0, v1 = acc[mf][nf][1] + b1;
            float v2 = acc[mf][nf][2] + b0, v3 = acc[mf][nf][3] + b1;
            if (doexp) {
                v0 = expf(v0); v1 = expf(v1); v2 = expf(v2); v3 = expf(v3);
                s0 += v0 + v2; s1 += v1 + v3;
            }
            if (!split) {
                float* c0 = Cf + (long)row * N + col;
                float2 p0; p0.x = v0; p0.y = v1; *(float2*)c0 = p0;
                float2 p1; p1.x = v2; p1.y = v3; *(float2*)(c0 + 8 * N) = p1;
            } else {
                __half2 p;
                p.x = __float2half_rn(v0); p.y = __float2half_rn(v1);
                *(__half2*)(Cs + (long)row * N + col) = p;
                p.x = __float2half_rn(v2); p.y = __float2half_rn(v3);
                *(__half2*)(Cs + (long)(row + 8) * N + col) = p;
            }
        }
        if (doexp) {
#pragma unroll
            for (int sh = 4; sh < 32; sh <<= 1) {
                s0 += __shfl_xor_sync(0xffffffffu, s0, sh);
                s1 += __shfl_xor_sync(0xffffffffu, s1, sh);
            }
            if ((lane >> 2) == 0) {
                const int b_idx = m0 >> 12;     // 4096 rows per batch
                atomicAdd(g_Z + b_idx * DIM + col, s0);
                atomicAdd(g_Z + b_idx * DIM + col + 1, s1);
            }
        }
    }
}

// ---------------------------------------------------------------------------
// init: zero softmax denominators + zero-bias
// ---------------------------------------------------------------------------
__global__ __launch_bounds__(256)
void init_stats()
{
    int i = blockIdx.x * 256 + threadIdx.x;
    if (i < BATCH * DIM) g_Z[i] = 0.f;
    if (i < DIM) g_zero[i] = 0.f;
}

// ---------------------------------------------------------------------------
// fused fp16 cast of z and x (one launch)
// ---------------------------------------------------------------------------
__global__ __launch_bounds__(256)
void cast2_f16(const float* __restrict__ in0, const float* __restrict__ in1,
               __half* __restrict__ out0, __half* __restrict__ out1, long total4)
{
    for (long idx = blockIdx.x * 256L + threadIdx.x; idx < 2 * total4; idx += gridDim.x * 256L) {
        const float* in = (idx < total4) ? in0 : in1;
        __half* out = (idx < total4) ? out0 : out1;
        long k = (idx < total4) ? idx : idx - total4;
        float4 v = ((const float4*)in)[k];
        __half2 p0, p1;
        p0.x = __float2half_rn(v.x); p0.y = __float2half_rn(v.y);
        p1.x = __float2half_rn(v.z); p1.y = __float2half_rn(v.w);
        ((__half2*)out)[k * 2] = p0;
        ((__half2*)out)[k * 2 + 1] = p1;
    }
}

// generic layout-preserving fp16 cast (w_q)
__global__ __launch_bounds__(256)
void cast_f16(const float* __restrict__ in, __half* __restrict__ out, long total4)
{
    for (long idx = blockIdx.x * 256L + threadIdx.x; idx < total4; idx += gridDim.x * 256L) {
        float4 v = ((const float4*)in)[idx];
        __half2 p0, p1;
        p0.x = __float2half_rn(v.x); p0.y = __float2half_rn(v.y);
        p1.x = __float2half_rn(v.z); p1.y = __float2half_rn(v.w);
        ((__half2*)out)[idx * 2] = p0;
        ((__half2*)out)[idx * 2 + 1] = p1;
    }
}

// Weights (transpose): in [1024,N] f32 -> out [N,1024] fp16
__global__ __launch_bounds__(256)
void split_wt(const float* __restrict__ in, __half* __restrict__ out, int N)
{
    __shared__ float t[32][33];
    const int n0 = blockIdx.x * 32, k0 = blockIdx.y * 32;
    const int tx = threadIdx.x & 31, ty = threadIdx.x >> 5;
#pragma unroll
    for (int i = 0; i < 4; i++)
        t[ty + i * 8][tx] = in[(long)(k0 + ty + i * 8) * N + n0 + tx];
    __syncthreads();
#pragma unroll
    for (int i = 0; i < 4; i++) {
        const int nn = ty + i * 8;
        out[(long)(n0 + nn) * DIM + k0 + tx] = __float2half_rn(t[tx][nn]);
    }
}

// ---------------------------------------------------------------------------
// Context via tensor cores: Cp[d][w] += ek^T[d][t] * v[t][w] over a T-slice.
// grid (BATCH*NH, TSPL), block 256 (8 warps: 4 d-tiles x 2 w-halves).
// ---------------------------------------------------------------------------
__global__ __launch_bounds__(256)
void context_mma()
{
    const int bh = blockIdx.x;
    const int tc = blockIdx.y;
    const int b = bh >> 4, h = bh & 15;
    const __half* kbase = g_kvh + (long)b * TLEN * (2 * DIM) + h * HD;
    const __half* vbase = kbase + DIM;

    __shared__ __align__(1024) char csm[2 * 16384];   // 2 stages x (ek 8K + v 8K)
    const uint32_t sb = su32(csm);
    const int tid = threadIdx.x, wid = tid >> 5, lane = tid & 31;
    const int tglob0 = tc * (TLEN / TSPL);            // 256-step slice

    auto load_chunk = [&](int c, int s) {
        const uint32_t se = sb + s * 16384;
        const uint32_t sv = se + 8192;
        const int tb = tglob0 + c * 64;
#pragma unroll
        for (int it = 0; it < 4; it++) {
            int i = tid + it * 256;
            if (it < 2) {
                int r = i >> 3, ch = (i & 7) * 16;
                CP16(se + SW128(r * 128 + ch), kbase + (long)(tb + r) * (2 * DIM) + ch / 2);
            } else {
                int j = i - 512;
                int r = j >> 3, ch = (j & 7) * 16;
                CP16(sv + SW128(r * 128 + ch), vbase + (long)(tb + r) * (2 * DIM) + ch / 2);
            }
        }
    };

    float acc[4][4];
#pragma unroll
    for (int nt = 0; nt < 4; nt++)
#pragma unroll
        for (int r = 0; r < 4; r++) acc[nt][r] = 0.f;

    const int dbase = (wid & 3) * 16;     // d-tile (M)
    const int wbase = (wid >> 2) * 32;    // w-half (N)
    const int a_t = (lane & 7) + ((lane >> 4) << 3);
    const int a_d16 = ((lane >> 3) & 1) * 16;         // bytes
    const int b_t = (lane & 7) + (((lane >> 3) & 1) << 3);
    const int b_w16 = (lane >> 4) * 16;               // bytes

    load_chunk(0, 0); CP_COMMIT();

    for (int c = 0; c < 4; c++) {
        if (c + 1 < 4) { load_chunk(c + 1, (c + 1) & 1); CP_COMMIT(); CP_WAIT(1); }
        else CP_WAIT(0);
        __syncthreads();
        const uint32_t se = sb + (c & 1) * 16384;
        const uint32_t sv = se + 8192;
#pragma unroll
        for (int tk = 0; tk < 4; tk++) {
            uint32_t af[4], bf[4][2];
            LDSM4T(af[0], af[1], af[2], af[3],
                   se + SW128((tk * 16 + a_t) * 128 + dbase * 2 + a_d16));
#pragma unroll
            for (int np = 0; np < 2; np++)
                LDSM4T(bf[np * 2][0], bf[np * 2][1], bf[np * 2 + 1][0], bf[np * 2 + 1][1],
                       sv + SW128((tk * 16 + b_t) * 128 + (wbase + np * 16) * 2 + b_w16));
#pragma unroll
            for (int nt = 0; nt < 4; nt++)
                MMA16816(acc[nt], af, bf[nt]);
        }
        __syncthreads();
    }

    float* outp = g_Cp + ((long)bh * TSPL + tc) * (HD * HD);
    const int d0 = dbase + (lane >> 2);
    const int w0 = wbase + (lane & 3) * 2;
#pragma unroll
    for (int nt = 0; nt < 4; nt++) {
        float2 p0; p0.x = acc[nt][0]; p0.y = acc[nt][1];
        *(float2*)(outp + d0 * 64 + w0 + nt * 8) = p0;
        float2 p1; p1.x = acc[nt][2]; p1.y = acc[nt][3];
        *(float2*)(outp + (d0 + 8) * 64 + w0 + nt * 8) = p1;
    }
}

__global__ __launch_bounds__(256)
void context_reduce()
{
    const int bh = blockIdx.x;
    const int b = bh >> 4, h = bh & 15;
    for (int i = threadIdx.x; i < HD * HD; i += 256) {
        float s = 0.f;
#pragma unroll
        for (int c = 0; c < TSPL; c++)
            s += g_Cp[((long)bh * TSPL + c) * (HD * HD) + i];
        const int d = i >> 6;
        g_Cn[(long)bh * (HD * HD) + i] = s / g_Z[b * DIM + h * HD + d];
    }
}

// ---------------------------------------------------------------------------
// Expand: Es_b[n][h*64+d] = sum_w Cn[b,h][d][w] * W_out[h*64+w][n]  (fp16 out,
// transposed directly via smem staging).
// grid = (DIM/128, BATCH*NH), block 256.
// ---------------------------------------------------------------------------
__global__ __launch_bounds__(256)
void expand_kernel(const float* __restrict__ w_out)
{
    const int bh = blockIdx.y;
    const int b = bh >> 4;
    const int h = bh & 15;
    const int cb = blockIdx.x * 128;

    __shared__ float pool[64 * 64 + 64 * 128];      // 48 KB
    float (*cs)[64]  = (float (*)[64])pool;
    float (*ws)[128] = (float (*)[128])(pool + 4096);

    const int tid = threadIdx.x;
    for (int i = tid; i < 1024; i += 256) {
        const int r = i >> 4;
        const int c = (i & 15) * 4;
        *(float4*)&cs[r][c] = *(const float4*)(g_Cn + (long)bh * 4096 + r * 64 + c);
    }
    for (int i = tid; i < 2048; i += 256) {
        const int r = i >> 5;
        const int c = (i & 31) * 4;
        *(float4*)&ws[r][c] = *(const float4*)(w_out + (long)(h * HD + r) * DIM + cb + c);
    }
    __syncthreads();

    const int tx = tid & 31;
    const int ty = tid >> 5;

    float acc[8][4];
#pragma unroll
    for (int rr = 0; rr < 8; rr++)
#pragma unroll
        for (int j = 0; j < 4; j++) acc[rr][j] = 0.f;

#pragma unroll 4
    for (int w = 0; w < 64; w++) {
        float4 wv = *(float4*)&ws[w][tx * 4];
#pragma unroll
        for (int rr = 0; rr < 8; rr++) {
            const float cv = cs[ty + rr * 8][w];
            acc[rr][0] = fmaf(cv, wv.x, acc[rr][0]);
            acc[rr][1] = fmaf(cv, wv.y, acc[rr][1]);
            acc[rr][2] = fmaf(cv, wv.z, acc[rr][2]);
            acc[rr][3] = fmaf(cv, wv.w, acc[rr][3]);
        }
    }
    __syncthreads();   // done reading cs/ws; reuse pool as transpose buffer

    float* tb = pool;  // [64 d][stride 129] floats
#pragma unroll
    for (int rr = 0; rr < 8; rr++) {
        const int row = ty + rr * 8;
#pragma unroll
        for (int j = 0; j < 4; j++)
            tb[row * 129 + tx * 4 + j] = acc[rr][j];
    }
    __syncthreads();

    __half* Eb = g_Es + (long)b * DIM * DIM;
    const int h2 = tid & 31;           // d-pair index
    const int nl0 = tid >> 5;
#pragma unroll
    for (int j = 0; j < 16; j++) {
        const int n_l = nl0 + j * 8;
        float f0 = tb[(2 * h2) * 129 + n_l];
        float f1 = tb[(2 * h2 + 1) * 129 + n_l];
        __half2 p; p.x = __float2half_rn(f0); p.y = __float2half_rn(f1);
        *(__half2*)(Eb + (long)(cb + n_l) * DIM + h * HD + 2 * h2) = p;
    }
}

// ---------------------------------------------------------------------------
// Folded bias: c_b[n] = b_out[n] + sum_j b_q[j] * E_b[j][n]
// One warp per (b, n). grid = 512 CTAs x 256 threads.
// ---------------------------------------------------------------------------
__global__ __launch_bounds__(256)
void cbias_kernel(const float* __restrict__ b_q, const float* __restrict__ b_out)
{
    const int gw = (blockIdx.x * 256 + threadIdx.x) >> 5;
    const int lane = threadIdx.x & 31;
    const int b = gw >> 10, n = gw & 1023;
    const __half* row = g_Es + (long)b * DIM * DIM + (long)n * DIM;
    float s = 0.f;
#pragma unroll 4
    for (int j = lane; j < DIM; j += 32)
        s += __half2float(row[j]) * __ldg(b_q + j);
#pragma unroll
    for (int sh = 16; sh; sh >>= 1)
        s += __shfl_xor_sync(0xffffffffu, s, sh);
    if (lane == 0)
        g_cb[b * DIM + n] = s + __ldg(b_out + n);
}

// ---------------------------------------------------------------------------
extern "C" void kernel_launch(void* const* d_in, const int* in_sizes, int n_in,
                              void* d_out, int out_size)
{
    const float* x     = (const float*)d_in[0];
    const float* z     = (const float*)d_in[1];
    const float* w_q   = (const float*)d_in[2];
    const float* b_q   = (const float*)d_in[3];
    const float* w_kv  = (const float*)d_in[4];
    const float* b_kv  = (const float*)d_in[5];
    const float* w_out = (const float*)d_in[6];
    const float* b_out = (const float*)d_in[7];
    float* out = (float*)d_out;

    float *zerov, *cb;
    __half *kvh, *zs, *xs, *wkvs, *wq16, *Es, *Fs;
    cudaGetSymbolAddress((void**)&kvh, g_kvh);
    cudaGetSymbolAddress((void**)&zerov, g_zero);
    cudaGetSymbolAddress((void**)&cb, g_cb);
    cudaGetSymbolAddress((void**)&zs, g_zs);
    cudaGetSymbolAddress((void**)&xs, g_xs);
    cudaGetSymbolAddress((void**)&wkvs, g_wkvs);
    cudaGetSymbolAddress((void**)&wq16, g_wq16);
    cudaGetSymbolAddress((void**)&Es, g_Es);
    cudaGetSymbolAddress((void**)&Fs, g_Fs);

    cudaFuncSetAttribute(gemm_mma, cudaFuncAttributeMaxDynamicSharedMemorySize, GSMEM);

    const int M = BATCH * TLEN;          // 16384
    const long tot4 = (long)M * DIM / 4;

    // 0. zero softmax denominators + zero-bias
    init_stats<<<16, 256>>>();
    // 1. weight prep: w_kv transpose -> fp16; w_q plain cast (B of F GEMM)
    { dim3 g(2 * DIM / 32, DIM / 32, 1); split_wt<<<g, 256>>>(w_kv, wkvs, 2 * DIM); }
    cast_f16<<<256, 256>>>(w_q, wq16, (long)DIM * DIM / 4);
    // 2. activation casts (z and x fused)
    cast2_f16<<<4096, 256>>>(z, x, zs, xs, tot4);
    // 3. kv = z @ w_kv + b_kv; k-half exponentiated in-epilogue, Z accumulated
    { dim3 g(2 * DIM / 256, M / 128, 1);
      gemm_mma<<<g, 512, GSMEM>>>(zs, wkvs, b_kv, nullptr, kvh, 2 * DIM, 1, DIM,
                                  0, 0, 0, 0); }
    // 4. context (tensor cores; partials over T, then reduce + normalize by Z)
    { dim3 g(BATCH * NH, TSPL); context_mma<<<g, 256>>>(); }
    context_reduce<<<BATCH * NH, 256>>>();
    // 5. Es_b = (blockdiag(Cn) @ W_out)^T fp16
    { dim3 g(DIM / 128, BATCH * NH); expand_kernel<<<g, 256>>>(w_out); }
    // 6. Fs_b[n][i] = sum_j Es_b[n][j] * w_q[i][j]   (F = Wq @ E, stored F^T)
    { dim3 g(DIM / 256, DIM / 128, BATCH);
      gemm_mma<<<g, 512, GSMEM>>>(Es, wq16, zerov, nullptr, Fs, DIM, 1, 0,
                                  (long)DIM * DIM, 0, (long)DIM * DIM, 0); }
    // 7. c_b = b_q @ E_b + b_out  (one warp per output)
    cbias_kernel<<<512, 256>>>(b_q, b_out);
    // 8. out_b = x_b @ F_b + c_b (batched, fp32 out)
    { dim3 g(DIM / 256, TLEN / 128, BATCH);
      gemm_mma<<<g, 512, GSMEM>>>(xs, Fs, cb, out, nullptr, DIM, 0, 0,
                                  (long)TLEN * DIM, (long)DIM * DIM, (long)TLEN * DIM, DIM); }
}

// round 17
// speedup vs baseline: 1.0994x; 1.0994x over previous
#include <cuda_runtime.h>
#include <cuda_fp16.h>
#include <cstdint>

// Problem constants
#define BATCH 4
#define TLEN  4096
#define DIM   1024
#define NH    16
#define HD    64
#define TSPL  16             // context T-slices

// ---------------------------------------------------------------------------
// Scratch (device globals; no allocation allowed)
// ---------------------------------------------------------------------------
__device__ static __align__(256) __half g_kvh[(long)BATCH * TLEN * 2 * DIM]; // ek|v fp16
__device__ static __align__(256) float g_Z [BATCH * DIM];
__device__ static __align__(256) float g_zero[DIM];
__device__ static __align__(256) float g_cb[BATCH * DIM];
__device__ static __align__(256) float g_Cp[BATCH * NH * TSPL * HD * HD];
__device__ static __align__(256) float g_Cn[BATCH * NH * HD * HD];

__device__ static __align__(256) __half g_zs [(long)BATCH * TLEN * DIM];
__device__ static __align__(256) __half g_xs [(long)BATCH * TLEN * DIM];
__device__ static __align__(256) __half g_wkvs[(long)2 * DIM * DIM];
__device__ static __align__(256) __half g_wq16[(long)DIM * DIM];       // w_q plain cast
__device__ static __align__(256) __half g_Es  [(long)BATCH * DIM * DIM]; // E^T fp16
__device__ static __align__(256) __half g_Fs  [(long)BATCH * DIM * DIM]; // F^T fp16

// ---------------------------------------------------------------------------
// Helpers
// ---------------------------------------------------------------------------
#define SW128(o) ((o) ^ (((o) >> 3) & 0x70))

static __device__ __forceinline__ uint32_t su32(const void* p) {
    uint32_t a;
    asm("{ .reg .u64 t; cvta.to.shared.u64 t, %1; cvt.u32.u64 %0, t; }" : "=r"(a) : "l"(p));
    return a;
}

#define CP16(dst, src)   asm volatile("cp.async.cg.shared.global [%0], [%1], 16;" :: "r"(dst), "l"(src))
#define CP_COMMIT()      asm volatile("cp.async.commit_group;" ::: "memory")
#define CP_WAIT(n)       asm volatile("cp.async.wait_group %0;" :: "n"(n) : "memory")

#define LDSM4(r0, r1, r2, r3, addr) \
    asm volatile("ldmatrix.sync.aligned.m8n8.x4.shared.b16 {%0,%1,%2,%3}, [%4];" \
        : "=r"(r0), "=r"(r1), "=r"(r2), "=r"(r3) : "r"(addr))

#define LDSM4T(r0, r1, r2, r3, addr) \
    asm volatile("ldmatrix.sync.aligned.m8n8.x4.trans.shared.b16 {%0,%1,%2,%3}, [%4];" \
        : "=r"(r0), "=r"(r1), "=r"(r2), "=r"(r3) : "r"(addr))

#define MMA16816(d, a, b) \
    asm volatile("mma.sync.aligned.m16n8k16.row.col.f32.f16.f16.f32 " \
        "{%0,%1,%2,%3},{%4,%5,%6,%7},{%8,%9},{%0,%1,%2,%3};" \
        : "+f"((d)[0]), "+f"((d)[1]), "+f"((d)[2]), "+f"((d)[3]) \
        : "r"((a)[0]), "r"((a)[1]), "r"((a)[2]), "r"((a)[3]), "r"((b)[0]), "r"((b)[1]))

// ---------------------------------------------------------------------------
// mma.sync fp16 GEMM:  C[M,N] = A[M,1024] * B[N,1024]^T + bias
// BM=128, BN=128, BK=64; 256 threads (8 warps, 2x4 of 64x32 tiles);
// 3-stage cp.async (96 KB smem, 2 CTA/SM), ONE sync per k-tile.
// split=1: write fp16 rows of width N into Cs (batched via sC).
// kexp>0: cols < kexp -> exp() after bias (no max shift; k~N(0,1) safe) and
//         per-(batch,col) partial sums atomicAdd'ed into g_Z.
// grid = (N/128, M/128, batch)
// ---------------------------------------------------------------------------
#define GNK      16
#define AH_OFF   0
#define BB_OFF   16384
#define STG_B    32768              // 32 KB
#define GSMEM    (3 * STG_B)        // 96 KB

extern __shared__ __align__(1024) char gsm_raw[];

__global__ __launch_bounds__(256, 2)
void gemm_mma(const __half* __restrict__ A, const __half* __restrict__ B,
              const float* __restrict__ bias, float* __restrict__ Cf,
              __half* __restrict__ Cs, int N, int split, int kexp,
              long sA, long sB, long sC, long sBias)
{
    A += blockIdx.z * sA; B += blockIdx.z * sB; bias += blockIdx.z * sBias;
    const long coff = (long)blockIdx.z * sC;
    if (Cf) Cf += coff;
    if (Cs) Cs += coff;
    const int m0 = blockIdx.y * 128;
    const int n0 = blockIdx.x * 128;
    const uint32_t sbase = su32(gsm_raw);
    const int tid = threadIdx.x, wid = tid >> 5, lane = tid & 31;

    const __half* Arow = A + (long)m0 * DIM;
    const __half* Brow = B + (long)n0 * DIM;

    auto load_tile = [&](int kt, int s) {
        const uint32_t st = sbase + s * STG_B;
        const int kc = kt * 64;
#pragma unroll
        for (int it = 0; it < 8; it++) {
            int i = tid + it * 256;
            if (it < 4) {                          // A: i in [0,1024)
                int row = i >> 3, ch = (i & 7) * 16;
                CP16(st + AH_OFF + SW128(row * 128 + ch),
                     Arow + (long)row * DIM + kc + ch / 2);
            } else {                               // B: j in [0,1024)
                int j = i - 1024;
                int row = j >> 3, ch = (j & 7) * 16;
                CP16(st + BB_OFF + SW128(row * 128 + ch),
                     Brow + (long)row * DIM + kc + ch / 2);
            }
        }
    };

    float acc[4][4][4];
#pragma unroll
    for (int mf = 0; mf < 4; mf++)
#pragma unroll
        for (int nf = 0; nf < 4; nf++)
#pragma unroll
            for (int r = 0; r < 4; r++) acc[mf][nf][r] = 0.f;

    const int wm = wid >> 2;                                      // 0..1
    const int wn = wid & 3;                                       // 0..3
    const int a_row = wm * 64 + (lane & 15);                      // + mf*16
    const int a_sec = (lane >> 4) * 16;
    const int b_row = wn * 32 + (lane & 7) + ((lane >> 4) << 3);  // + nf2*16
    const int b_sec = ((lane >> 3) & 1) * 16;

    // prologue: stages 0, 1
    load_tile(0, 0); CP_COMMIT();
    load_tile(1, 1); CP_COMMIT();

    int s_cur = 0, s_nxt = 2;
    for (int kt = 0; kt < GNK; kt++) {
        if (kt < GNK - 1) CP_WAIT(1); else CP_WAIT(0);
        __syncthreads();                 // stage s_cur ready; compute kt-1 done
        if (kt + 2 < GNK) { load_tile(kt + 2, s_nxt); CP_COMMIT(); }

        const uint32_t st = sbase + s_cur * STG_B;
#pragma unroll
        for (int ks = 0; ks < 4; ks++) {
            uint32_t bf[4][2];
#pragma unroll
            for (int nf2 = 0; nf2 < 2; nf2++)
                LDSM4(bf[nf2 * 2][0], bf[nf2 * 2][1], bf[nf2 * 2 + 1][0], bf[nf2 * 2 + 1][1],
                      st + BB_OFF + SW128((b_row + nf2 * 16) * 128 + ks * 32 + b_sec));
#pragma unroll
            for (int mf = 0; mf < 4; mf++) {
                uint32_t ah[4];
                LDSM4(ah[0], ah[1], ah[2], ah[3],
                      st + AH_OFF + SW128((a_row + mf * 16) * 128 + ks * 32 + a_sec));
#pragma unroll
                for (int nf = 0; nf < 4; nf++)
                    MMA16816(acc[mf][nf], ah, bf[nf]);
            }
        }
        if (++s_cur == 3) s_cur = 0;
        if (++s_nxt == 3) s_nxt = 0;
    }

    // Epilogue
#pragma unroll
    for (int nf = 0; nf < 4; nf++) {
        const int col = n0 + wn * 32 + nf * 8 + (lane & 3) * 2;
        const float b0 = __ldg(bias + col), b1 = __ldg(bias + col + 1);
        const bool doexp = (col < kexp);     // uniform per 8-col group
        float s0 = 0.f, s1 = 0.f;
#pragma unroll
        for (int mf = 0; mf < 4; mf++) {
            const int row = m0 + wm * 64 + mf * 16 + (lane >> 2);
            float v0 = acc[mf][nf][0] + b0, v1 = acc[mf][nf][1] + b1;
            float v2 = acc[mf][nf][2] + b0, v3 = acc[mf][nf][3] + b1;
            if (doexp) {
                v0 = expf(v0); v1 = expf(v1); v2 = expf(v2); v3 = expf(v3);
                s0 += v0 + v2; s1 += v1 + v3;
            }
            if (!split) {
                float* c0 = Cf + (long)row * N + col;
                float2 p0; p0.x = v0; p0.y = v1; *(float2*)c0 = p0;
                float2 p1; p1.x = v2; p1.y = v3; *(float2*)(c0 + 8 * N) = p1;
            } else {
                __half2 p;
                p.x = __float2half_rn(v0); p.y = __float2half_rn(v1);
                *(__half2*)(Cs + (long)row * N + col) = p;
                p.x = __float2half_rn(v2); p.y = __float2half_rn(v3);
                *(__half2*)(Cs + (long)(row + 8) * N + col) = p;
            }
        }
        if (doexp) {
#pragma unroll
            for (int sh = 4; sh < 32; sh <<= 1) {
                s0 += __shfl_xor_sync(0xffffffffu, s0, sh);
                s1 += __shfl_xor_sync(0xffffffffu, s1, sh);
            }
            if ((lane >> 2) == 0) {
                const int b_idx = m0 >> 12;     // 4096 rows per batch
                atomicAdd(g_Z + b_idx * DIM + col, s0);
                atomicAdd(g_Z + b_idx * DIM + col + 1, s1);
            }
        }
    }
}

// ---------------------------------------------------------------------------
// init: zero softmax denominators + zero-bias
// ---------------------------------------------------------------------------
__global__ __launch_bounds__(256)
void init_stats()
{
    int i = blockIdx.x * 256 + threadIdx.x;
    if (i < BATCH * DIM) g_Z[i] = 0.f;
    if (i < DIM) g_zero[i] = 0.f;
}

// ---------------------------------------------------------------------------
// fused fp16 cast of z and x (one launch)
// ---------------------------------------------------------------------------
__global__ __launch_bounds__(256)
void cast2_f16(const float* __restrict__ in0, const float* __restrict__ in1,
               __half* __restrict__ out0, __half* __restrict__ out1, long total4)
{
    for (long idx = blockIdx.x * 256L + threadIdx.x; idx < 2 * total4; idx += gridDim.x * 256L) {
        const float* in = (idx < total4) ? in0 : in1;
        __half* out = (idx < total4) ? out0 : out1;
        long k = (idx < total4) ? idx : idx - total4;
        float4 v = ((const float4*)in)[k];
        __half2 p0, p1;
        p0.x = __float2half_rn(v.x); p0.y = __float2half_rn(v.y);
        p1.x = __float2half_rn(v.z); p1.y = __float2half_rn(v.w);
        ((__half2*)out)[k * 2] = p0;
        ((__half2*)out)[k * 2 + 1] = p1;
    }
}

// generic layout-preserving fp16 cast (w_q)
__global__ __launch_bounds__(256)
void cast_f16(const float* __restrict__ in, __half* __restrict__ out, long total4)
{
    for (long idx = blockIdx.x * 256L + threadIdx.x; idx < total4; idx += gridDim.x * 256L) {
        float4 v = ((const float4*)in)[idx];
        __half2 p0, p1;
        p0.x = __float2half_rn(v.x); p0.y = __float2half_rn(v.y);
        p1.x = __float2half_rn(v.z); p1.y = __float2half_rn(v.w);
        ((__half2*)out)[idx * 2] = p0;
        ((__half2*)out)[idx * 2 + 1] = p1;
    }
}

// Weights (transpose): in [1024,N] f32 -> out [N,1024] fp16
__global__ __launch_bounds__(256)
void split_wt(const float* __restrict__ in, __half* __restrict__ out, int N)
{
    __shared__ float t[32][33];
    const int n0 = blockIdx.x * 32, k0 = blockIdx.y * 32;
    const int tx = threadIdx.x & 31, ty = threadIdx.x >> 5;
#pragma unroll
    for (int i = 0; i < 4; i++)
        t[ty + i * 8][tx] = in[(long)(k0 + ty + i * 8) * N + n0 + tx];
    __syncthreads();
#pragma unroll
    for (int i = 0; i < 4; i++) {
        const int nn = ty + i * 8;
        out[(long)(n0 + nn) * DIM + k0 + tx] = __float2half_rn(t[tx][nn]);
    }
}

// ---------------------------------------------------------------------------
// Context via tensor cores: Cp[d][w] += ek^T[d][t] * v[t][w] over a T-slice.
// grid (BATCH*NH, TSPL), block 256 (8 warps: 4 d-tiles x 2 w-halves).
// ---------------------------------------------------------------------------
__global__ __launch_bounds__(256)
void context_mma()
{
    const int bh = blockIdx.x;
    const int tc = blockIdx.y;
    const int b = bh >> 4, h = bh & 15;
    const __half* kbase = g_kvh + (long)b * TLEN * (2 * DIM) + h * HD;
    const __half* vbase = kbase + DIM;

    __shared__ __align__(1024) char csm[2 * 16384];   // 2 stages x (ek 8K + v 8K)
    const uint32_t sb = su32(csm);
    const int tid = threadIdx.x, wid = tid >> 5, lane = tid & 31;
    const int tglob0 = tc * (TLEN / TSPL);            // 256-step slice

    auto load_chunk = [&](int c, int s) {
        const uint32_t se = sb + s * 16384;
        const uint32_t sv = se + 8192;
        const int tb = tglob0 + c * 64;
#pragma unroll
        for (int it = 0; it < 4; it++) {
            int i = tid + it * 256;
            if (it < 2) {
                int r = i >> 3, ch = (i & 7) * 16;
                CP16(se + SW128(r * 128 + ch), kbase + (long)(tb + r) * (2 * DIM) + ch / 2);
            } else {
                int j = i - 512;
                int r = j >> 3, ch = (j & 7) * 16;
                CP16(sv + SW128(r * 128 + ch), vbase + (long)(tb + r) * (2 * DIM) + ch / 2);
            }
        }
    };

    float acc[4][4];
#pragma unroll
    for (int nt = 0; nt < 4; nt++)
#pragma unroll
        for (int r = 0; r < 4; r++) acc[nt][r] = 0.f;

    const int dbase = (wid & 3) * 16;     // d-tile (M)
    const int wbase = (wid >> 2) * 32;    // w-half (N)
    const int a_t = (lane & 7) + ((lane >> 4) << 3);
    const int a_d16 = ((lane >> 3) & 1) * 16;         // bytes
    const int b_t = (lane & 7) + (((lane >> 3) & 1) << 3);
    const int b_w16 = (lane >> 4) * 16;               // bytes

    load_chunk(0, 0); CP_COMMIT();

    for (int c = 0; c < 4; c++) {
        if (c + 1 < 4) { load_chunk(c + 1, (c + 1) & 1); CP_COMMIT(); CP_WAIT(1); }
        else CP_WAIT(0);
        __syncthreads();
        const uint32_t se = sb + (c & 1) * 16384;
        const uint32_t sv = se + 8192;
#pragma unroll
        for (int tk = 0; tk < 4; tk++) {
            uint32_t af[4], bf[4][2];
            LDSM4T(af[0], af[1], af[2], af[3],
                   se + SW128((tk * 16 + a_t) * 128 + dbase * 2 + a_d16));
#pragma unroll
            for (int np = 0; np < 2; np++)
                LDSM4T(bf[np * 2][0], bf[np * 2][1], bf[np * 2 + 1][0], bf[np * 2 + 1][1],
                       sv + SW128((tk * 16 + b_t) * 128 + (wbase + np * 16) * 2 + b_w16));
#pragma unroll
            for (int nt = 0; nt < 4; nt++)
                MMA16816(acc[nt], af, bf[nt]);
        }
        __syncthreads();
    }

    float* outp = g_Cp + ((long)bh * TSPL + tc) * (HD * HD);
    const int d0 = dbase + (lane >> 2);
    const int w0 = wbase + (lane & 3) * 2;
#pragma unroll
    for (int nt = 0; nt < 4; nt++) {
        float2 p0; p0.x = acc[nt][0]; p0.y = acc[nt][1];
        *(float2*)(outp + d0 * 64 + w0 + nt * 8) = p0;
        float2 p1; p1.x = acc[nt][2]; p1.y = acc[nt][3];
        *(float2*)(outp + (d0 + 8) * 64 + w0 + nt * 8) = p1;
    }
}

__global__ __launch_bounds__(256)
void context_reduce()
{
    const int bh = blockIdx.x;
    const int b = bh >> 4, h = bh & 15;
    for (int i = threadIdx.x; i < HD * HD; i += 256) {
        float s = 0.f;
#pragma unroll
        for (int c = 0; c < TSPL; c++)
            s += g_Cp[((long)bh * TSPL + c) * (HD * HD) + i];
        const int d = i >> 6;
        g_Cn[(long)bh * (HD * HD) + i] = s / g_Z[b * DIM + h * HD + d];
    }
}

// ---------------------------------------------------------------------------
// Expand: Es_b[n][h*64+d] = sum_w Cn[b,h][d][w] * W_out[h*64+w][n]  (fp16 out,
// transposed directly via smem staging).
// grid = (DIM/128, BATCH*NH), block 256.
// ---------------------------------------------------------------------------
__global__ __launch_bounds__(256)
void expand_kernel(const float* __restrict__ w_out)
{
    const int bh = blockIdx.y;
    const int b = bh >> 4;
    const int h = bh & 15;
    const int cb = blockIdx.x * 128;

    __shared__ float pool[64 * 64 + 64 * 128];      // 48 KB
    float (*cs)[64]  = (float (*)[64])pool;
    float (*ws)[128] = (float (*)[128])(pool + 4096);

    const int tid = threadIdx.x;
    for (int i = tid; i < 1024; i += 256) {
        const int r = i >> 4;
        const int c = (i & 15) * 4;
        *(float4*)&cs[r][c] = *(const float4*)(g_Cn + (long)bh * 4096 + r * 64 + c);
    }
    for (int i = tid; i < 2048; i += 256) {
        const int r = i >> 5;
        const int c = (i & 31) * 4;
        *(float4*)&ws[r][c] = *(const float4*)(w_out + (long)(h * HD + r) * DIM + cb + c);
    }
    __syncthreads();

    const int tx = tid & 31;
    const int ty = tid >> 5;

    float acc[8][4];
#pragma unroll
    for (int rr = 0; rr < 8; rr++)
#pragma unroll
        for (int j = 0; j < 4; j++) acc[rr][j] = 0.f;

#pragma unroll 4
    for (int w = 0; w < 64; w++) {
        float4 wv = *(float4*)&ws[w][tx * 4];
#pragma unroll
        for (int rr = 0; rr < 8; rr++) {
            const float cv = cs[ty + rr * 8][w];
            acc[rr][0] = fmaf(cv, wv.x, acc[rr][0]);
            acc[rr][1] = fmaf(cv, wv.y, acc[rr][1]);
            acc[rr][2] = fmaf(cv, wv.z, acc[rr][2]);
            acc[rr][3] = fmaf(cv, wv.w, acc[rr][3]);
        }
    }
    __syncthreads();   // done reading cs/ws; reuse pool as transpose buffer

    float* tb = pool;  // [64 d][stride 129] floats
#pragma unroll
    for (int rr = 0; rr < 8; rr++) {
        const int row = ty + rr * 8;
#pragma unroll
        for (int j = 0; j < 4; j++)
            tb[row * 129 + tx * 4 + j] = acc[rr][j];
    }
    __syncthreads();

    __half* Eb = g_Es + (long)b * DIM * DIM;
    const int h2 = tid & 31;           // d-pair index
    const int nl0 = tid >> 5;
#pragma unroll
    for (int j = 0; j < 16; j++) {
        const int n_l = nl0 + j * 8;
        float f0 = tb[(2 * h2) * 129 + n_l];
        float f1 = tb[(2 * h2 + 1) * 129 + n_l];
        __half2 p; p.x = __float2half_rn(f0); p.y = __float2half_rn(f1);
        *(__half2*)(Eb + (long)(cb + n_l) * DIM + h * HD + 2 * h2) = p;
    }
}

// ---------------------------------------------------------------------------
// Folded bias: c_b[n] = b_out[n] + sum_j b_q[j] * E_b[j][n]
// One warp per (b, n). grid = 512 CTAs x 256 threads.
// ---------------------------------------------------------------------------
__global__ __launch_bounds__(256)
void cbias_kernel(const float* __restrict__ b_q, const float* __restrict__ b_out)
{
    const int gw = (blockIdx.x * 256 + threadIdx.x) >> 5;
    const int lane = threadIdx.x & 31;
    const int b = gw >> 10, n = gw & 1023;
    const __half* row = g_Es + (long)b * DIM * DIM + (long)n * DIM;
    float s = 0.f;
#pragma unroll 4
    for (int j = lane; j < DIM; j += 32)
        s += __half2float(row[j]) * __ldg(b_q + j);
#pragma unroll
    for (int sh = 16; sh; sh >>= 1)
        s += __shfl_xor_sync(0xffffffffu, s, sh);
    if (lane == 0)
        g_cb[b * DIM + n] = s + __ldg(b_out + n);
}

// ---------------------------------------------------------------------------
extern "C" void kernel_launch(void* const* d_in, const int* in_sizes, int n_in,
                              void* d_out, int out_size)
{
    const float* x     = (const float*)d_in[0];
    const float* z     = (const float*)d_in[1];
    const float* w_q   = (const float*)d_in[2];
    const float* b_q   = (const float*)d_in[3];
    const float* w_kv  = (const float*)d_in[4];
    const float* b_kv  = (const float*)d_in[5];
    const float* w_out = (const float*)d_in[6];
    const float* b_out = (const float*)d_in[7];
    float* out = (float*)d_out;

    float *zerov, *cb;
    __half *kvh, *zs, *xs, *wkvs, *wq16, *Es, *Fs;
    cudaGetSymbolAddress((void**)&kvh, g_kvh);
    cudaGetSymbolAddress((void**)&zerov, g_zero);
    cudaGetSymbolAddress((void**)&cb, g_cb);
    cudaGetSymbolAddress((void**)&zs, g_zs);
    cudaGetSymbolAddress((void**)&xs, g_xs);
    cudaGetSymbolAddress((void**)&wkvs, g_wkvs);
    cudaGetSymbolAddress((void**)&wq16, g_wq16);
    cudaGetSymbolAddress((void**)&Es, g_Es);
    cudaGetSymbolAddress((void**)&Fs, g_Fs);

    cudaFuncSetAttribute(gemm_mma, cudaFuncAttributeMaxDynamicSharedMemorySize, GSMEM);

    const int M = BATCH * TLEN;          // 16384
    const long tot4 = (long)M * DIM / 4;

    // 0. zero softmax denominators + zero-bias
    init_stats<<<16, 256>>>();
    // 1. weight prep: w_kv transpose -> fp16; w_q plain cast (B of F GEMM)
    { dim3 g(2 * DIM / 32, DIM / 32, 1); split_wt<<<g, 256>>>(w_kv, wkvs, 2 * DIM); }
    cast_f16<<<256, 256>>>(w_q, wq16, (long)DIM * DIM / 4);
    // 2. activation casts (z and x fused)
    cast2_f16<<<4096, 256>>>(z, x, zs, xs, tot4);
    // 3. kv = z @ w_kv + b_kv; k-half exponentiated in-epilogue, Z accumulated
    { dim3 g(2 * DIM / 128, M / 128, 1);
      gemm_mma<<<g, 256, GSMEM>>>(zs, wkvs, b_kv, nullptr, kvh, 2 * DIM, 1, DIM,
                                  0, 0, 0, 0); }
    // 4. context (tensor cores; partials over T, then reduce + normalize by Z)
    { dim3 g(BATCH * NH, TSPL); context_mma<<<g, 256>>>(); }
    context_reduce<<<BATCH * NH, 256>>>();
    // 5. Es_b = (blockdiag(Cn) @ W_out)^T fp16
    { dim3 g(DIM / 128, BATCH * NH); expand_kernel<<<g, 256>>>(w_out); }
    // 6. Fs_b[n][i] = sum_j Es_b[n][j] * w_q[i][j]   (F = Wq @ E, stored F^T)
    { dim3 g(DIM / 128, DIM / 128, BATCH);
      gemm_mma<<<g, 256, GSMEM>>>(Es, wq16, zerov, nullptr, Fs, DIM, 1, 0,
                                  (long)DIM * DIM, 0, (long)DIM * DIM, 0); }
    // 7. c_b = b_q @ E_b + b_out  (one warp per output)
    cbias_kernel<<<512, 256>>>(b_q, b_out);
    // 8. out_b = x_b @ F_b + c_b (batched, fp32 out)
    { dim3 g(DIM / 128, TLEN / 128, BATCH);
      gemm_mma<<<g, 256, GSMEM>>>(xs, Fs, cb, out, nullptr, DIM, 0, 0,
                                  (long)TLEN * DIM, (long)DIM * DIM, (long)TLEN * DIM, DIM); }
}